// round 1
// baseline (speedup 1.0000x reference)
#include <cuda_runtime.h>
#include <cstdint>

#define B_    15
#define NW_   64
#define NT    144
#define DIM   384
#define HEADS 12
#define HD    32
#define TOK   (B_ * NW_ * NT)     // 138240
#define QKVC  (3 * DIM)           // 1152

// ---- device scratch (no allocations allowed) ----
__device__ float g_q[(size_t)B_ * NW_ * HEADS * NT * HD];   // [bw*H+h][n][d]
__device__ float g_k[(size_t)B_ * NW_ * HEADS * NT * HD];
__device__ float g_v[(size_t)B_ * NW_ * HEADS * NT * HD];
__device__ float g_ao[(size_t)TOK * DIM];                   // attention output (pre-proj)
__device__ int   g_piT[NT * NT];                            // transposed position index

// ---------------------------------------------------------------------------
__global__ void transpose_pi_kernel(const int* __restrict__ pi) {
    int idx = blockIdx.x * blockDim.x + threadIdx.x;
    if (idx < NT * NT) {
        int i = idx / NT, j = idx % NT;
        g_piT[j * NT + i] = pi[idx];
    }
}

// ---------------------------------------------------------------------------
// QKV GEMM: A (TOK x DIM) @ W (DIM x 1152) + bias, scatter into g_q/g_k/g_v.
// Tile: 128(M) x 64(N), BK=16, 256 threads, 8x4 outputs per thread.
__global__ __launch_bounds__(256) void gemm_qkv_kernel(
    const float* __restrict__ A, const float* __restrict__ Bm,
    const float* __restrict__ bias)
{
    __shared__ float As[16 * 128];   // transposed: As[k][m]
    __shared__ float Bs[16 * 64];    // Bs[k][n]

    const int tid = threadIdx.x;
    const int row_base = (tid >> 4) << 3;   // 0..120
    const int col_base = (tid & 15) << 2;   // 0..60
    const int bm = blockIdx.y * 128;
    const int bn = blockIdx.x * 64;

    float acc[8][4];
#pragma unroll
    for (int r = 0; r < 8; r++)
#pragma unroll
        for (int c = 0; c < 4; c++) acc[r][c] = 0.f;

    for (int k0 = 0; k0 < DIM; k0 += 16) {
#pragma unroll
        for (int it = 0; it < 2; it++) {
            int f = tid + it * 256;
            int r = f >> 2;
            int k4 = (f & 3) << 2;
            float4 av = *(const float4*)&A[(size_t)(bm + r) * DIM + k0 + k4];
            As[(k4 + 0) * 128 + r] = av.x;
            As[(k4 + 1) * 128 + r] = av.y;
            As[(k4 + 2) * 128 + r] = av.z;
            As[(k4 + 3) * 128 + r] = av.w;
        }
        {
            int kk = tid >> 4;
            int c4 = (tid & 15) << 2;
            *(float4*)&Bs[kk * 64 + c4] =
                *(const float4*)&Bm[(size_t)(k0 + kk) * QKVC + bn + c4];
        }
        __syncthreads();
#pragma unroll
        for (int kk = 0; kk < 16; kk++) {
            float4 a0 = *(float4*)&As[kk * 128 + row_base];
            float4 a1 = *(float4*)&As[kk * 128 + row_base + 4];
            float4 b0 = *(float4*)&Bs[kk * 64 + col_base];
            float a[8] = {a0.x, a0.y, a0.z, a0.w, a1.x, a1.y, a1.z, a1.w};
            float bb[4] = {b0.x, b0.y, b0.z, b0.w};
#pragma unroll
            for (int r = 0; r < 8; r++)
#pragma unroll
                for (int c = 0; c < 4; c++) acc[r][c] += a[r] * bb[c];
        }
        __syncthreads();
    }

    // Epilogue: add bias, scale q, scatter into head-major layout.
    const int cg0 = bn + col_base;         // 0..1148, multiple of 4
    const int which = cg0 / DIM;           // 0=q 1=k 2=v (constant across 4 cols)
    const int rem = cg0 % DIM;
    const int hh = rem / HD;
    const int dd = rem % HD;               // multiple of 4
    float* dst = (which == 0) ? g_q : ((which == 1) ? g_k : g_v);
    const float sc = (which == 0) ? 0.17677669529663687f : 1.0f;
    float4 bv;
    bv.x = bias[cg0 + 0]; bv.y = bias[cg0 + 1];
    bv.z = bias[cg0 + 2]; bv.w = bias[cg0 + 3];

#pragma unroll
    for (int r = 0; r < 8; r++) {
        int t = bm + row_base + r;
        int bw = t / NT;
        int n  = t - bw * NT;
        float4 o;
        o.x = (acc[r][0] + bv.x) * sc;
        o.y = (acc[r][1] + bv.y) * sc;
        o.z = (acc[r][2] + bv.z) * sc;
        o.w = (acc[r][3] + bv.w) * sc;
        *(float4*)&dst[((size_t)(bw * HEADS + hh) * NT + n) * HD + dd] = o;
    }
}

// ---------------------------------------------------------------------------
// Fused attention: one block per (b, w, h). K/V in smem; each of 144 threads
// owns one query row; single-pass online softmax; bias gathered from table.
__global__ __launch_bounds__(160) void attn_kernel(
    const float* __restrict__ mask, const float* __restrict__ bias_table)
{
    __shared__ float ks[NT * HD];
    __shared__ float vs[NT * HD];

    const int bx = blockIdx.x;
    const int h = bx % HEADS;
    const int w = (bx / HEADS) % NW_;
    const int b = bx / (HEADS * NW_);
    const int bw = b * NW_ + w;
    const size_t head_base = (size_t)(bw * HEADS + h) * NT * HD;

    const int tid = threadIdx.x;
    {
        const float4* kg = (const float4*)(g_k + head_base);
        const float4* vg = (const float4*)(g_v + head_base);
        float4* ks4 = (float4*)ks;
        float4* vs4 = (float4*)vs;
        for (int i = tid; i < NT * HD / 4; i += 160) {
            ks4[i] = kg[i];
            vs4[i] = vg[i];
        }
    }
    __syncthreads();

    if (tid >= NT) return;

    // load this thread's (already scaled) q row
    float qr[HD];
    {
        const float4* qg = (const float4*)(g_q + head_base + (size_t)tid * HD);
#pragma unroll
        for (int i = 0; i < HD / 4; i++) {
            float4 t4 = qg[i];
            qr[i * 4 + 0] = t4.x; qr[i * 4 + 1] = t4.y;
            qr[i * 4 + 2] = t4.z; qr[i * 4 + 3] = t4.w;
        }
    }

    const float* mrow = mask + ((size_t)b * NT + tid) * NT;
    const int who = w * HEADS + h;                  // offset into (nw, H) plane
    const int* piTcol = g_piT + tid;                // piT[j*NT + i], coalesced in j

    float m = -1e30f, l = 0.f;
    float accv[HD];
#pragma unroll
    for (int d = 0; d < HD; d++) accv[d] = 0.f;

    for (int j = 0; j < NT; j++) {
        const float* kj = &ks[j * HD];
        float s0 = 0.f, s1 = 0.f, s2 = 0.f, s3 = 0.f;
#pragma unroll
        for (int d = 0; d < HD; d += 4) {
            s0 += qr[d + 0] * kj[d + 0];
            s1 += qr[d + 1] * kj[d + 1];
            s2 += qr[d + 2] * kj[d + 2];
            s3 += qr[d + 3] * kj[d + 3];
        }
        int p = piTcol[j * NT];
        float s = (s0 + s1) + (s2 + s3)
                  + __ldg(&bias_table[(size_t)p * (NW_ * HEADS) + who])
                  + mrow[j];

        float mn = fmaxf(m, s);
        float corr = __expf(m - mn);
        float pe = __expf(s - mn);
        l = l * corr + pe;
        const float* vj = &vs[j * HD];
#pragma unroll
        for (int d = 0; d < HD; d++)
            accv[d] = accv[d] * corr + pe * vj[d];
        m = mn;
    }

    const float inv = 1.f / l;
    float* o = g_ao + ((size_t)(bw * NT) + tid) * DIM + h * HD;
#pragma unroll
    for (int d = 0; d < HD; d += 4) {
        float4 t4;
        t4.x = accv[d + 0] * inv; t4.y = accv[d + 1] * inv;
        t4.z = accv[d + 2] * inv; t4.w = accv[d + 3] * inv;
        *(float4*)&o[d] = t4;
    }
}

// ---------------------------------------------------------------------------
// Proj GEMM: g_ao (TOK x DIM) @ w_proj (DIM x DIM) + b_proj -> out
__global__ __launch_bounds__(256) void gemm_proj_kernel(
    const float* __restrict__ Bm, const float* __restrict__ bias,
    float* __restrict__ out)
{
    __shared__ float As[16 * 128];
    __shared__ float Bs[16 * 64];

    const int tid = threadIdx.x;
    const int row_base = (tid >> 4) << 3;
    const int col_base = (tid & 15) << 2;
    const int bm = blockIdx.y * 128;
    const int bn = blockIdx.x * 64;
    const float* A = g_ao;

    float acc[8][4];
#pragma unroll
    for (int r = 0; r < 8; r++)
#pragma unroll
        for (int c = 0; c < 4; c++) acc[r][c] = 0.f;

    for (int k0 = 0; k0 < DIM; k0 += 16) {
#pragma unroll
        for (int it = 0; it < 2; it++) {
            int f = tid + it * 256;
            int r = f >> 2;
            int k4 = (f & 3) << 2;
            float4 av = *(const float4*)&A[(size_t)(bm + r) * DIM + k0 + k4];
            As[(k4 + 0) * 128 + r] = av.x;
            As[(k4 + 1) * 128 + r] = av.y;
            As[(k4 + 2) * 128 + r] = av.z;
            As[(k4 + 3) * 128 + r] = av.w;
        }
        {
            int kk = tid >> 4;
            int c4 = (tid & 15) << 2;
            *(float4*)&Bs[kk * 64 + c4] =
                *(const float4*)&Bm[(size_t)(k0 + kk) * DIM + bn + c4];
        }
        __syncthreads();
#pragma unroll
        for (int kk = 0; kk < 16; kk++) {
            float4 a0 = *(float4*)&As[kk * 128 + row_base];
            float4 a1 = *(float4*)&As[kk * 128 + row_base + 4];
            float4 b0 = *(float4*)&Bs[kk * 64 + col_base];
            float a[8] = {a0.x, a0.y, a0.z, a0.w, a1.x, a1.y, a1.z, a1.w};
            float bb[4] = {b0.x, b0.y, b0.z, b0.w};
#pragma unroll
            for (int r = 0; r < 8; r++)
#pragma unroll
                for (int c = 0; c < 4; c++) acc[r][c] += a[r] * bb[c];
        }
        __syncthreads();
    }

    const int cg0 = bn + col_base;
    float4 bv;
    bv.x = bias[cg0 + 0]; bv.y = bias[cg0 + 1];
    bv.z = bias[cg0 + 2]; bv.w = bias[cg0 + 3];
#pragma unroll
    for (int r = 0; r < 8; r++) {
        int t = bm + row_base + r;
        float4 o;
        o.x = acc[r][0] + bv.x;
        o.y = acc[r][1] + bv.y;
        o.z = acc[r][2] + bv.z;
        o.w = acc[r][3] + bv.w;
        *(float4*)&out[(size_t)t * DIM + cg0] = o;
    }
}

// ---------------------------------------------------------------------------
extern "C" void kernel_launch(void* const* d_in, const int* in_sizes, int n_in,
                              void* d_out, int out_size)
{
    const float* x          = (const float*)d_in[0];
    const float* mask       = (const float*)d_in[1];
    const float* w_qkv      = (const float*)d_in[2];
    const float* b_qkv      = (const float*)d_in[3];
    const float* w_proj     = (const float*)d_in[4];
    const float* b_proj     = (const float*)d_in[5];
    const float* bias_table = (const float*)d_in[6];
    const int*   pi         = (const int*)d_in[7];
    float* out = (float*)d_out;

    transpose_pi_kernel<<<(NT * NT + 255) / 256, 256>>>(pi);

    dim3 g1(QKVC / 64, TOK / 128);
    gemm_qkv_kernel<<<g1, 256>>>(x, w_qkv, b_qkv);

    attn_kernel<<<B_ * NW_ * HEADS, 160>>>(mask, bias_table);

    dim3 g2(DIM / 64, TOK / 128);
    gemm_proj_kernel<<<g2, 256>>>(w_proj, b_proj, out);
}

// round 3
// speedup vs baseline: 1.5154x; 1.5154x over previous
#include <cuda_runtime.h>
#include <cstdint>

#define B_    15
#define NW_   64
#define NT    144
#define DIM   384
#define HEADS 12
#define HD    32
#define TOK   (B_ * NW_ * NT)     // 138240
#define QKVC  (3 * DIM)           // 1152

// ---- device scratch ----
__device__ float g_q[(size_t)B_ * NW_ * HEADS * NT * HD];
__device__ float g_k[(size_t)B_ * NW_ * HEADS * NT * HD];
__device__ float g_v[(size_t)B_ * NW_ * HEADS * NT * HD];
__device__ float g_ao[(size_t)TOK * DIM];
__device__ int   g_piT[NT * NT];
__device__ float g_wT_qkv[(size_t)QKVC * DIM];   // [n][k], tf32-rounded
__device__ float g_wT_proj[(size_t)DIM * DIM];   // [n][k], tf32-rounded

// ---------------------------------------------------------------------------
__device__ __forceinline__ uint32_t smem_u32(const void* p) {
    uint32_t a;
    asm("{ .reg .u64 t; cvta.to.shared.u64 t, %1; cvt.u32.u64 %0, t; }"
        : "=r"(a) : "l"(p));
    return a;
}
__device__ __forceinline__ float to_tf32(float x) {
    float r;
    asm("cvt.rna.tf32.f32 %0, %1;" : "=f"(r) : "f"(x));
    return r;
}
__device__ __forceinline__ void ldsm4(uint32_t* r, uint32_t addr) {
    asm volatile("ldmatrix.sync.aligned.m8n8.x4.shared.b16 {%0,%1,%2,%3}, [%4];"
                 : "=r"(r[0]), "=r"(r[1]), "=r"(r[2]), "=r"(r[3]) : "r"(addr));
}
__device__ __forceinline__ void mma_tf32(float* c, const uint32_t* a,
                                         uint32_t b0, uint32_t b1) {
    asm volatile(
        "mma.sync.aligned.m16n8k8.row.col.f32.tf32.tf32.f32 "
        "{%0,%1,%2,%3}, {%4,%5,%6,%7}, {%8,%9}, {%0,%1,%2,%3};"
        : "+f"(c[0]), "+f"(c[1]), "+f"(c[2]), "+f"(c[3])
        : "r"(a[0]), "r"(a[1]), "r"(a[2]), "r"(a[3]), "r"(b0), "r"(b1));
}

// ---------------------------------------------------------------------------
__global__ void transpose_pi_kernel(const int* __restrict__ pi) {
    int idx = blockIdx.x * blockDim.x + threadIdx.x;
    if (idx < NT * NT) {
        int i = idx / NT, j = idx % NT;
        g_piT[j * NT + i] = pi[idx];
    }
}

__global__ void prep_w_kernel(const float* __restrict__ wq,
                              const float* __restrict__ wp) {
    int i = blockIdx.x * blockDim.x + threadIdx.x;
    if (i < QKVC * DIM) {
        int n = i / DIM, k = i % DIM;
        g_wT_qkv[i] = to_tf32(wq[(size_t)k * QKVC + n]);
    } else {
        int j = i - QKVC * DIM;
        if (j < DIM * DIM) {
            int n = j / DIM, k = j % DIM;
            g_wT_proj[j] = to_tf32(wp[(size_t)k * DIM + n]);
        }
    }
}

// ---------------------------------------------------------------------------
// tf32 mma.sync GEMM: 128x128 CTA tile, BK=16, 8 warps (4Mx2N), warp 32x64.
// Smem rows padded to 20 floats (80B pitch): ldmatrix bank-group (5r+c)%8
// is distinct over any 8 consecutive rows -> conflict-free.
// MODE 0: A=x, B=g_wT_qkv -> scatter q/k/v (+bias, q*scale)
// MODE 1: A=g_ao, B=g_wT_proj -> out (+bias)
// ---------------------------------------------------------------------------
#define BPITCH 20
template <int NTOT, int MODE>
__global__ __launch_bounds__(256, 1) void gemm_mma_kernel(
    const float* __restrict__ Ain, const float* __restrict__ bias,
    float* __restrict__ out)
{
    __shared__ float As[2][128 * BPITCH];
    __shared__ float Bs[2][128 * BPITCH];

    const int tid = threadIdx.x;
    const int wid = tid >> 5;
    const int lane = tid & 31;
    const int warp_m = wid >> 1;       // 0..3
    const int warp_n = wid & 1;        // 0..1
    const int bn = blockIdx.x * 128;
    const int bm = blockIdx.y * 128;

    const float* A = (MODE == 0) ? Ain : g_ao;
    const float* Bt = (MODE == 0) ? g_wT_qkv : g_wT_proj;

    const int f0 = tid, f1 = tid + 256;
    const int am0 = f0 >> 2, ac0 = (f0 & 3) << 2;
    const int am1 = f1 >> 2, ac1 = (f1 & 3) << 2;

    float acc[2][8][4];
#pragma unroll
    for (int mt = 0; mt < 2; mt++)
#pragma unroll
        for (int nt = 0; nt < 8; nt++)
#pragma unroll
            for (int i = 0; i < 4; i++) acc[mt][nt][i] = 0.f;

    const int rowA_off = (warp_m * 32 + (lane & 15)) * BPITCH + (lane >> 4) * 4;
    const int rowB_off = (warp_n * 64 + (lane & 15)) * BPITCH + (lane >> 4) * 4;
    const uint32_t sA0 = smem_u32(&As[0][0]);
    const uint32_t sB0 = smem_u32(&Bs[0][0]);
    const uint32_t stage_bytes = 128 * BPITCH * 4;

    // prologue: stage 0
    {
        float4 a0 = *(const float4*)&A[(size_t)(bm + am0) * DIM + ac0];
        float4 a1 = *(const float4*)&A[(size_t)(bm + am1) * DIM + ac1];
        float4 b0 = *(const float4*)&Bt[(size_t)(bn + am0) * DIM + ac0];
        float4 b1 = *(const float4*)&Bt[(size_t)(bn + am1) * DIM + ac1];
        a0.x = to_tf32(a0.x); a0.y = to_tf32(a0.y); a0.z = to_tf32(a0.z); a0.w = to_tf32(a0.w);
        a1.x = to_tf32(a1.x); a1.y = to_tf32(a1.y); a1.z = to_tf32(a1.z); a1.w = to_tf32(a1.w);
        *(float4*)&As[0][am0 * BPITCH + ac0] = a0;
        *(float4*)&As[0][am1 * BPITCH + ac1] = a1;
        *(float4*)&Bs[0][am0 * BPITCH + ac0] = b0;
        *(float4*)&Bs[0][am1 * BPITCH + ac1] = b1;
    }
    __syncthreads();

    const int NSTAGE = DIM / 16;   // 24
    float4 pa0, pa1, pb0, pb1;

    for (int s = 0; s < NSTAGE; s++) {
        const int p = s & 1;
        if (s < NSTAGE - 1) {
            const int ks = (s + 1) * 16;
            pa0 = *(const float4*)&A[(size_t)(bm + am0) * DIM + ks + ac0];
            pa1 = *(const float4*)&A[(size_t)(bm + am1) * DIM + ks + ac1];
            pb0 = *(const float4*)&Bt[(size_t)(bn + am0) * DIM + ks + ac0];
            pb1 = *(const float4*)&Bt[(size_t)(bn + am1) * DIM + ks + ac1];
        }
        const uint32_t sA = sA0 + p * stage_bytes;
        const uint32_t sB = sB0 + p * stage_bytes;
#pragma unroll
        for (int kk = 0; kk < 2; kk++) {
            uint32_t ua[2][4], ub[4][4];
#pragma unroll
            for (int mt = 0; mt < 2; mt++)
                ldsm4(ua[mt], sA + (rowA_off + mt * 16 * BPITCH + kk * 8) * 4);
#pragma unroll
            for (int g = 0; g < 4; g++)
                ldsm4(ub[g], sB + (rowB_off + g * 16 * BPITCH + kk * 8) * 4);
#pragma unroll
            for (int mt = 0; mt < 2; mt++)
#pragma unroll
                for (int nt = 0; nt < 8; nt++)
                    mma_tf32(acc[mt][nt], ua[mt], ub[nt >> 1][nt & 1],
                             ub[nt >> 1][(nt & 1) + 2]);
        }
        if (s < NSTAGE - 1) {
            const int q = 1 - p;
            pa0.x = to_tf32(pa0.x); pa0.y = to_tf32(pa0.y); pa0.z = to_tf32(pa0.z); pa0.w = to_tf32(pa0.w);
            pa1.x = to_tf32(pa1.x); pa1.y = to_tf32(pa1.y); pa1.z = to_tf32(pa1.z); pa1.w = to_tf32(pa1.w);
            *(float4*)&As[q][am0 * BPITCH + ac0] = pa0;
            *(float4*)&As[q][am1 * BPITCH + ac1] = pa1;
            *(float4*)&Bs[q][am0 * BPITCH + ac0] = pb0;
            *(float4*)&Bs[q][am1 * BPITCH + ac1] = pb1;
            __syncthreads();
        }
    }

    // ---------------- epilogue ----------------
    const int colb = warp_n * 64 + 2 * (lane & 3);
    if (MODE == 0) {
        const int which = bn / DIM;
        float* dst = (which == 0) ? g_q : (which == 1) ? g_k : g_v;
        const float sc = (which == 0) ? 0.17677669529663687f : 1.0f;
        const int rembase = (bn - which * DIM) + colb;
#pragma unroll
        for (int nt = 0; nt < 8; nt++) {
            const int rem = rembase + nt * 8;
            const int hh = rem >> 5, dd = rem & 31;
            const float b0 = __ldg(&bias[which * DIM + rem]);
            const float b1 = __ldg(&bias[which * DIM + rem + 1]);
#pragma unroll
            for (int mt = 0; mt < 2; mt++) {
#pragma unroll
                for (int rr = 0; rr < 2; rr++) {
                    const int m = bm + warp_m * 32 + mt * 16 + (lane >> 2) + rr * 8;
                    const int bw = m / NT, n = m - (m / NT) * NT;
                    float2 v;
                    v.x = (acc[mt][nt][rr * 2 + 0] + b0) * sc;
                    v.y = (acc[mt][nt][rr * 2 + 1] + b1) * sc;
                    *(float2*)&dst[((size_t)(bw * HEADS + hh) * NT + n) * HD + dd] = v;
                }
            }
        }
    } else {
#pragma unroll
        for (int nt = 0; nt < 8; nt++) {
            const int col = bn + colb + nt * 8;
            const float b0 = __ldg(&bias[col]);
            const float b1 = __ldg(&bias[col + 1]);
#pragma unroll
            for (int mt = 0; mt < 2; mt++) {
#pragma unroll
                for (int rr = 0; rr < 2; rr++) {
                    const int m = bm + warp_m * 32 + mt * 16 + (lane >> 2) + rr * 8;
                    float2 v;
                    v.x = acc[mt][nt][rr * 2 + 0] + b0;
                    v.y = acc[mt][nt][rr * 2 + 1] + b1;
                    *(float2*)&out[(size_t)m * DIM + col] = v;
                }
            }
        }
    }
}

// ---------------------------------------------------------------------------
// Fused attention: block per (b,w,h); K/V in smem; 1 query row per thread;
// bounded scores -> plain exp (no running max).
// ---------------------------------------------------------------------------
__global__ __launch_bounds__(160) void attn_kernel(
    const float* __restrict__ mask, const float* __restrict__ bias_table)
{
    __shared__ float ks[NT * HD];
    __shared__ float vs[NT * HD];

    const int bx = blockIdx.x;
    const int h = bx % HEADS;
    const int w = (bx / HEADS) % NW_;
    const int b = bx / (HEADS * NW_);
    const int bw = b * NW_ + w;
    const size_t head_base = (size_t)(bw * HEADS + h) * NT * HD;

    const int tid = threadIdx.x;
    {
        const float4* kg = (const float4*)(g_k + head_base);
        const float4* vg = (const float4*)(g_v + head_base);
        float4* ks4 = (float4*)ks;
        float4* vs4 = (float4*)vs;
        for (int i = tid; i < NT * HD / 4; i += 160) {
            ks4[i] = kg[i];
            vs4[i] = vg[i];
        }
    }
    __syncthreads();
    if (tid >= NT) return;

    float qr[HD];
    {
        const float4* qg = (const float4*)(g_q + head_base + (size_t)tid * HD);
#pragma unroll
        for (int i = 0; i < HD / 4; i++) {
            float4 t4 = qg[i];
            qr[i * 4 + 0] = t4.x; qr[i * 4 + 1] = t4.y;
            qr[i * 4 + 2] = t4.z; qr[i * 4 + 3] = t4.w;
        }
    }

    const float* mrow = mask + ((size_t)b * NT + tid) * NT;
    const int who = w * HEADS + h;
    const int* piTcol = g_piT + tid;

    float l = 0.f;
    float accv[HD];
#pragma unroll
    for (int d = 0; d < HD; d++) accv[d] = 0.f;

    for (int j = 0; j < NT; j++) {
        const float* kj = &ks[j * HD];
        float s0 = 0.f, s1 = 0.f, s2 = 0.f, s3 = 0.f;
#pragma unroll
        for (int d = 0; d < HD; d += 4) {
            s0 += qr[d + 0] * kj[d + 0];
            s1 += qr[d + 1] * kj[d + 1];
            s2 += qr[d + 2] * kj[d + 2];
            s3 += qr[d + 3] * kj[d + 3];
        }
        int p = piTcol[j * NT];
        float s = (s0 + s1) + (s2 + s3)
                  + __ldg(&bias_table[(size_t)p * (NW_ * HEADS) + who])
                  + mrow[j];
        float pe = __expf(s);
        l += pe;
        const float* vj = &vs[j * HD];
#pragma unroll
        for (int d = 0; d < HD; d++)
            accv[d] += pe * vj[d];
    }

    const float inv = 1.f / l;
    float* o = g_ao + ((size_t)(bw * NT) + tid) * DIM + h * HD;
#pragma unroll
    for (int d = 0; d < HD; d += 4) {
        float4 t4;
        t4.x = accv[d + 0] * inv; t4.y = accv[d + 1] * inv;
        t4.z = accv[d + 2] * inv; t4.w = accv[d + 3] * inv;
        *(float4*)&o[d] = t4;
    }
}

// ---------------------------------------------------------------------------
extern "C" void kernel_launch(void* const* d_in, const int* in_sizes, int n_in,
                              void* d_out, int out_size)
{
    const float* x          = (const float*)d_in[0];
    const float* mask       = (const float*)d_in[1];
    const float* w_qkv      = (const float*)d_in[2];
    const float* b_qkv      = (const float*)d_in[3];
    const float* w_proj     = (const float*)d_in[4];
    const float* b_proj     = (const float*)d_in[5];
    const float* bias_table = (const float*)d_in[6];
    const int*   pi         = (const int*)d_in[7];
    float* out = (float*)d_out;

    transpose_pi_kernel<<<(NT * NT + 255) / 256, 256>>>(pi);
    prep_w_kernel<<<(QKVC * DIM + DIM * DIM + 255) / 256, 256>>>(w_qkv, w_proj);

    dim3 g1(QKVC / 128, TOK / 128);
    gemm_mma_kernel<QKVC, 0><<<g1, 256>>>(x, b_qkv, out);

    attn_kernel<<<B_ * NW_ * HEADS, 160>>>(mask, bias_table);

    dim3 g2(DIM / 128, TOK / 128);
    gemm_mma_kernel<DIM, 1><<<g2, 256>>>(nullptr, b_proj, out);
}

// round 4
// speedup vs baseline: 2.4762x; 1.6340x over previous
#include <cuda_runtime.h>
#include <cstdint>

#define B_    15
#define NW_   64
#define NT    144
#define DIM   384
#define HEADS 12
#define HD    32
#define TOK   (B_ * NW_ * NT)     // 138240
#define QKVC  (3 * DIM)           // 1152
#define WH    (NW_ * HEADS)       // 768
#define NTSQ  (NT * NT)           // 20736

// ---- device scratch ----
__device__ float g_q[(size_t)B_ * NW_ * HEADS * NT * HD];
__device__ float g_k[(size_t)B_ * NW_ * HEADS * NT * HD];
__device__ float g_v[(size_t)B_ * NW_ * HEADS * NT * HD];
__device__ float g_ao[(size_t)TOK * DIM];
__device__ float g_wT_qkv[(size_t)QKVC * DIM];   // [n][k], tf32-rounded
__device__ float g_wT_proj[(size_t)DIM * DIM];   // [n][k], tf32-rounded
__device__ float g_bias[(size_t)WH * NTSQ];      // [w*H+h][i*144+j]

// ---------------------------------------------------------------------------
__device__ __forceinline__ uint32_t smem_u32(const void* p) {
    uint32_t a;
    asm("{ .reg .u64 t; cvta.to.shared.u64 t, %1; cvt.u32.u64 %0, t; }"
        : "=r"(a) : "l"(p));
    return a;
}
__device__ __forceinline__ float to_tf32(float x) {
    float r;
    asm("cvt.rna.tf32.f32 %0, %1;" : "=f"(r) : "f"(x));
    return r;
}
__device__ __forceinline__ void ldsm4(uint32_t* r, uint32_t addr) {
    asm volatile("ldmatrix.sync.aligned.m8n8.x4.shared.b16 {%0,%1,%2,%3}, [%4];"
                 : "=r"(r[0]), "=r"(r[1]), "=r"(r[2]), "=r"(r[3]) : "r"(addr));
}
__device__ __forceinline__ void mma_tf32(float* c, const uint32_t* a,
                                         uint32_t b0, uint32_t b1) {
    asm volatile(
        "mma.sync.aligned.m16n8k8.row.col.f32.tf32.tf32.f32 "
        "{%0,%1,%2,%3}, {%4,%5,%6,%7}, {%8,%9}, {%0,%1,%2,%3};"
        : "+f"(c[0]), "+f"(c[1]), "+f"(c[2]), "+f"(c[3])
        : "r"(a[0]), "r"(a[1]), "r"(a[2]), "r"(a[3]), "r"(b0), "r"(b1));
}

// ---------------------------------------------------------------------------
__global__ void prep_w_kernel(const float* __restrict__ wq,
                              const float* __restrict__ wp) {
    int i = blockIdx.x * blockDim.x + threadIdx.x;
    if (i < QKVC * DIM) {
        int n = i / DIM, k = i % DIM;
        g_wT_qkv[i] = to_tf32(wq[(size_t)k * QKVC + n]);
    } else {
        int j = i - QKVC * DIM;
        if (j < DIM * DIM) {
            int n = j / DIM, k = j % DIM;
            g_wT_proj[j] = to_tf32(wp[(size_t)k * DIM + n]);
        }
    }
}

// Materialize g_bias[wh][ij] = bias_table[pi[ij]*768 + wh] via smem transpose.
__global__ void prep_bias_kernel(const float* __restrict__ bt,
                                 const int* __restrict__ pi) {
    __shared__ float t[32][33];
    const int tx = threadIdx.x, ty = threadIdx.y;
    const int ij = blockIdx.x * 32 + ty;
    const int wh = blockIdx.y * 32 + tx;
    t[ty][tx] = __ldg(&bt[(size_t)__ldg(&pi[ij]) * WH + wh]);
    __syncthreads();
    const int wh_o = blockIdx.y * 32 + ty;
    const int ij_o = blockIdx.x * 32 + tx;
    g_bias[(size_t)wh_o * NTSQ + ij_o] = t[tx][ty];
}

// ---------------------------------------------------------------------------
// tf32 mma.sync GEMM (unchanged from R3): 128x128 tile, BK=16, 8 warps.
// ---------------------------------------------------------------------------
#define BPITCH 20
template <int NTOT, int MODE>
__global__ __launch_bounds__(256, 1) void gemm_mma_kernel(
    const float* __restrict__ Ain, const float* __restrict__ bias,
    float* __restrict__ out)
{
    __shared__ float As[2][128 * BPITCH];
    __shared__ float Bs[2][128 * BPITCH];

    const int tid = threadIdx.x;
    const int wid = tid >> 5;
    const int lane = tid & 31;
    const int warp_m = wid >> 1;
    const int warp_n = wid & 1;
    const int bn = blockIdx.x * 128;
    const int bm = blockIdx.y * 128;

    const float* A = (MODE == 0) ? Ain : g_ao;
    const float* Bt = (MODE == 0) ? g_wT_qkv : g_wT_proj;

    const int f0 = tid, f1 = tid + 256;
    const int am0 = f0 >> 2, ac0 = (f0 & 3) << 2;
    const int am1 = f1 >> 2, ac1 = (f1 & 3) << 2;

    float acc[2][8][4];
#pragma unroll
    for (int mt = 0; mt < 2; mt++)
#pragma unroll
        for (int nt = 0; nt < 8; nt++)
#pragma unroll
            for (int i = 0; i < 4; i++) acc[mt][nt][i] = 0.f;

    const int rowA_off = (warp_m * 32 + (lane & 15)) * BPITCH + (lane >> 4) * 4;
    const int rowB_off = (warp_n * 64 + (lane & 15)) * BPITCH + (lane >> 4) * 4;
    const uint32_t sA0 = smem_u32(&As[0][0]);
    const uint32_t sB0 = smem_u32(&Bs[0][0]);
    const uint32_t stage_bytes = 128 * BPITCH * 4;

    {
        float4 a0 = *(const float4*)&A[(size_t)(bm + am0) * DIM + ac0];
        float4 a1 = *(const float4*)&A[(size_t)(bm + am1) * DIM + ac1];
        float4 b0 = *(const float4*)&Bt[(size_t)(bn + am0) * DIM + ac0];
        float4 b1 = *(const float4*)&Bt[(size_t)(bn + am1) * DIM + ac1];
        a0.x = to_tf32(a0.x); a0.y = to_tf32(a0.y); a0.z = to_tf32(a0.z); a0.w = to_tf32(a0.w);
        a1.x = to_tf32(a1.x); a1.y = to_tf32(a1.y); a1.z = to_tf32(a1.z); a1.w = to_tf32(a1.w);
        *(float4*)&As[0][am0 * BPITCH + ac0] = a0;
        *(float4*)&As[0][am1 * BPITCH + ac1] = a1;
        *(float4*)&Bs[0][am0 * BPITCH + ac0] = b0;
        *(float4*)&Bs[0][am1 * BPITCH + ac1] = b1;
    }
    __syncthreads();

    const int NSTAGE = DIM / 16;
    float4 pa0, pa1, pb0, pb1;

    for (int s = 0; s < NSTAGE; s++) {
        const int p = s & 1;
        if (s < NSTAGE - 1) {
            const int ks = (s + 1) * 16;
            pa0 = *(const float4*)&A[(size_t)(bm + am0) * DIM + ks + ac0];
            pa1 = *(const float4*)&A[(size_t)(bm + am1) * DIM + ks + ac1];
            pb0 = *(const float4*)&Bt[(size_t)(bn + am0) * DIM + ks + ac0];
            pb1 = *(const float4*)&Bt[(size_t)(bn + am1) * DIM + ks + ac1];
        }
        const uint32_t sA = sA0 + p * stage_bytes;
        const uint32_t sB = sB0 + p * stage_bytes;
#pragma unroll
        for (int kk = 0; kk < 2; kk++) {
            uint32_t ua[2][4], ub[4][4];
#pragma unroll
            for (int mt = 0; mt < 2; mt++)
                ldsm4(ua[mt], sA + (rowA_off + mt * 16 * BPITCH + kk * 8) * 4);
#pragma unroll
            for (int g = 0; g < 4; g++)
                ldsm4(ub[g], sB + (rowB_off + g * 16 * BPITCH + kk * 8) * 4);
#pragma unroll
            for (int mt = 0; mt < 2; mt++)
#pragma unroll
                for (int nt = 0; nt < 8; nt++)
                    mma_tf32(acc[mt][nt], ua[mt], ub[nt >> 1][nt & 1],
                             ub[nt >> 1][(nt & 1) + 2]);
        }
        if (s < NSTAGE - 1) {
            const int q = 1 - p;
            pa0.x = to_tf32(pa0.x); pa0.y = to_tf32(pa0.y); pa0.z = to_tf32(pa0.z); pa0.w = to_tf32(pa0.w);
            pa1.x = to_tf32(pa1.x); pa1.y = to_tf32(pa1.y); pa1.z = to_tf32(pa1.z); pa1.w = to_tf32(pa1.w);
            *(float4*)&As[q][am0 * BPITCH + ac0] = pa0;
            *(float4*)&As[q][am1 * BPITCH + ac1] = pa1;
            *(float4*)&Bs[q][am0 * BPITCH + ac0] = pb0;
            *(float4*)&Bs[q][am1 * BPITCH + ac1] = pb1;
            __syncthreads();
        }
    }

    const int colb = warp_n * 64 + 2 * (lane & 3);
    if (MODE == 0) {
        const int which = bn / DIM;
        float* dst = (which == 0) ? g_q : (which == 1) ? g_k : g_v;
        const float sc = (which == 0) ? 0.17677669529663687f : 1.0f;
        const int rembase = (bn - which * DIM) + colb;
#pragma unroll
        for (int nt = 0; nt < 8; nt++) {
            const int rem = rembase + nt * 8;
            const int hh = rem >> 5, dd = rem & 31;
            const float b0 = __ldg(&bias[which * DIM + rem]);
            const float b1 = __ldg(&bias[which * DIM + rem + 1]);
#pragma unroll
            for (int mt = 0; mt < 2; mt++) {
#pragma unroll
                for (int rr = 0; rr < 2; rr++) {
                    const int m = bm + warp_m * 32 + mt * 16 + (lane >> 2) + rr * 8;
                    const int bw = m / NT, n = m - (m / NT) * NT;
                    float2 v;
                    v.x = (acc[mt][nt][rr * 2 + 0] + b0) * sc;
                    v.y = (acc[mt][nt][rr * 2 + 1] + b1) * sc;
                    *(float2*)&dst[((size_t)(bw * HEADS + hh) * NT + n) * HD + dd] = v;
                }
            }
        }
    } else {
#pragma unroll
        for (int nt = 0; nt < 8; nt++) {
            const int col = bn + colb + nt * 8;
            const float b0 = __ldg(&bias[col]);
            const float b1 = __ldg(&bias[col + 1]);
#pragma unroll
            for (int mt = 0; mt < 2; mt++) {
#pragma unroll
                for (int rr = 0; rr < 2; rr++) {
                    const int m = bm + warp_m * 32 + mt * 16 + (lane >> 2) + rr * 8;
                    float2 v;
                    v.x = acc[mt][nt][rr * 2 + 0] + b0;
                    v.y = acc[mt][nt][rr * 2 + 1] + b1;
                    *(float2*)&out[(size_t)m * DIM + col] = v;
                }
            }
        }
    }
}

// ---------------------------------------------------------------------------
// Tensor-core attention: block = (b,w,h), 288 threads = 9 warps,
// warp wi owns query rows [16*wi, 16*wi+16).
//  Phase 1: S = Q@K^T (mma tf32) + bias + mask -> exp -> P (smem), row sums
//           stay in registers (quad shuffle).
//  Phase 2: O = P@V (mma tf32, V transposed in smem), scale by 1/rowsum.
// Smem pitches: Q/K 36 floats, Vt/P 148 floats -> ldmatrix conflict-free.
// ---------------------------------------------------------------------------
#define QK_PITCH 36
#define P_PITCH  148
#define SM_Q  0
#define SM_K  (NT * QK_PITCH)                 // 5184
#define SM_VT (SM_K + NT * QK_PITCH)          // 10368
#define SM_P  (SM_VT + HD * P_PITCH)          // 15104
#define SM_TOT_F (SM_P + NT * P_PITCH)        // 36416 floats = 145664 B

__global__ __launch_bounds__(288, 1) void attn_mma_kernel(
    const float* __restrict__ mask)
{
    extern __shared__ float sm[];
    float* Qs = sm + SM_Q;
    float* Ks = sm + SM_K;
    float* Vt = sm + SM_VT;
    float* Ps = sm + SM_P;

    const int bx = blockIdx.x;
    const int h = bx % HEADS;
    const int w = (bx / HEADS) % NW_;
    const int b = bx / WH;
    const int bw = b * NW_ + w;
    const size_t head_base = (size_t)(bw * HEADS + h) * NT * HD;

    const int tid = threadIdx.x;
    const int wid = tid >> 5;
    const int lane = tid & 31;

    // ---- load Q, K (tf32-rounded), V transposed ----
    for (int i = tid; i < NT * HD / 4; i += 288) {
        const int r = i >> 3, c4 = (i & 7) << 2;
        float4 q4 = *(const float4*)&g_q[head_base + (size_t)r * HD + c4];
        float4 k4 = *(const float4*)&g_k[head_base + (size_t)r * HD + c4];
        q4.x = to_tf32(q4.x); q4.y = to_tf32(q4.y); q4.z = to_tf32(q4.z); q4.w = to_tf32(q4.w);
        k4.x = to_tf32(k4.x); k4.y = to_tf32(k4.y); k4.z = to_tf32(k4.z); k4.w = to_tf32(k4.w);
        *(float4*)&Qs[r * QK_PITCH + c4] = q4;
        *(float4*)&Ks[r * QK_PITCH + c4] = k4;
        float4 v4 = *(const float4*)&g_v[head_base + (size_t)r * HD + c4];
        Vt[(c4 + 0) * P_PITCH + r] = to_tf32(v4.x);
        Vt[(c4 + 1) * P_PITCH + r] = to_tf32(v4.y);
        Vt[(c4 + 2) * P_PITCH + r] = to_tf32(v4.z);
        Vt[(c4 + 3) * P_PITCH + r] = to_tf32(v4.w);
    }
    __syncthreads();

    const uint32_t sQ = smem_u32(Qs);
    const uint32_t sK = smem_u32(Ks);
    const uint32_t sV = smem_u32(Vt);
    const uint32_t sP = smem_u32(Ps);

    const int i0 = wid * 16;
    const int lrow = lane >> 2;             // 0..7
    const int lcol = (lane & 3) * 2;        // 0,2,4,6

    // ---- Phase 1: S = Q @ K^T ----
    float acc[18][4];
#pragma unroll
    for (int nt = 0; nt < 18; nt++)
#pragma unroll
        for (int e = 0; e < 4; e++) acc[nt][e] = 0.f;

#pragma unroll
    for (int ks = 0; ks < 4; ks++) {
        uint32_t ua[4];
        ldsm4(ua, sQ + ((i0 + (lane & 15)) * QK_PITCH + (lane >> 4) * 4 + ks * 8) * 4);
#pragma unroll
        for (int g = 0; g < 9; g++) {
            uint32_t ub[4];
            ldsm4(ub, sK + ((g * 16 + (lane & 15)) * QK_PITCH + (lane >> 4) * 4 + ks * 8) * 4);
            mma_tf32(acc[2 * g + 0], ua, ub[0], ub[2]);
            mma_tf32(acc[2 * g + 1], ua, ub[1], ub[3]);
        }
    }

    // ---- softmax epilogue: bias + mask, exp, row sums, store P ----
    const float* bp = g_bias + (size_t)(w * HEADS + h) * NTSQ;
    const float* mp = mask + (size_t)b * NTSQ;
    const int r0 = i0 + lrow;
    const int r1 = r0 + 8;
    float s0 = 0.f, s1 = 0.f;
#pragma unroll
    for (int nt = 0; nt < 18; nt++) {
        const int j = nt * 8 + lcol;
        const float2 bb0 = *(const float2*)&bp[r0 * NT + j];
        const float2 bb1 = *(const float2*)&bp[r1 * NT + j];
        const float2 mm0 = *(const float2*)&mp[r0 * NT + j];
        const float2 mm1 = *(const float2*)&mp[r1 * NT + j];
        float p00 = __expf(acc[nt][0] + bb0.x + mm0.x);
        float p01 = __expf(acc[nt][1] + bb0.y + mm0.y);
        float p10 = __expf(acc[nt][2] + bb1.x + mm1.x);
        float p11 = __expf(acc[nt][3] + bb1.y + mm1.y);
        s0 += p00 + p01;
        s1 += p10 + p11;
        float2 w0; w0.x = to_tf32(p00); w0.y = to_tf32(p01);
        float2 w1; w1.x = to_tf32(p10); w1.y = to_tf32(p11);
        *(float2*)&Ps[r0 * P_PITCH + j] = w0;
        *(float2*)&Ps[r1 * P_PITCH + j] = w1;
    }
    s0 += __shfl_xor_sync(0xffffffffu, s0, 1);
    s0 += __shfl_xor_sync(0xffffffffu, s0, 2);
    s1 += __shfl_xor_sync(0xffffffffu, s1, 1);
    s1 += __shfl_xor_sync(0xffffffffu, s1, 2);
    const float inv0 = 1.f / s0;
    const float inv1 = 1.f / s1;

    __syncthreads();

    // ---- Phase 2: O = P @ V ----
    float oc[4][4];
#pragma unroll
    for (int nt = 0; nt < 4; nt++)
#pragma unroll
        for (int e = 0; e < 4; e++) oc[nt][e] = 0.f;

#pragma unroll
    for (int ks = 0; ks < 18; ks++) {
        uint32_t ua[4], ub0[4], ub1[4];
        ldsm4(ua, sP + ((i0 + (lane & 15)) * P_PITCH + (lane >> 4) * 4 + ks * 8) * 4);
        ldsm4(ub0, sV + (((lane & 15)) * P_PITCH + (lane >> 4) * 4 + ks * 8) * 4);
        ldsm4(ub1, sV + ((16 + (lane & 15)) * P_PITCH + (lane >> 4) * 4 + ks * 8) * 4);
        mma_tf32(oc[0], ua, ub0[0], ub0[2]);
        mma_tf32(oc[1], ua, ub0[1], ub0[3]);
        mma_tf32(oc[2], ua, ub1[0], ub1[2]);
        mma_tf32(oc[3], ua, ub1[1], ub1[3]);
    }

    // ---- write O (normalized) to g_ao ----
#pragma unroll
    for (int nt = 0; nt < 4; nt++) {
        const int d = nt * 8 + lcol;
        float2 v0; v0.x = oc[nt][0] * inv0; v0.y = oc[nt][1] * inv0;
        float2 v1; v1.x = oc[nt][2] * inv1; v1.y = oc[nt][3] * inv1;
        *(float2*)&g_ao[((size_t)(bw * NT) + r0) * DIM + h * HD + d] = v0;
        *(float2*)&g_ao[((size_t)(bw * NT) + r1) * DIM + h * HD + d] = v1;
    }
}

// ---------------------------------------------------------------------------
extern "C" void kernel_launch(void* const* d_in, const int* in_sizes, int n_in,
                              void* d_out, int out_size)
{
    const float* x          = (const float*)d_in[0];
    const float* mask       = (const float*)d_in[1];
    const float* w_qkv      = (const float*)d_in[2];
    const float* b_qkv      = (const float*)d_in[3];
    const float* w_proj     = (const float*)d_in[4];
    const float* b_proj     = (const float*)d_in[5];
    const float* bias_table = (const float*)d_in[6];
    const int*   pi         = (const int*)d_in[7];
    float* out = (float*)d_out;

    const int ATTN_SMEM = SM_TOT_F * 4;   // 145664 B
    cudaFuncSetAttribute(attn_mma_kernel,
                         cudaFuncAttributeMaxDynamicSharedMemorySize, ATTN_SMEM);

    prep_w_kernel<<<(QKVC * DIM + DIM * DIM + 255) / 256, 256>>>(w_qkv, w_proj);

    dim3 bt(32, 32);
    dim3 bg(NTSQ / 32, WH / 32);
    prep_bias_kernel<<<bg, bt>>>(bias_table, pi);

    dim3 g1(QKVC / 128, TOK / 128);
    gemm_mma_kernel<QKVC, 0><<<g1, 256>>>(x, b_qkv, out);

    attn_mma_kernel<<<B_ * WH, 288, ATTN_SMEM>>>(mask);

    dim3 g2(DIM / 128, TOK / 128);
    gemm_mma_kernel<DIM, 1><<<g2, 256>>>(nullptr, b_proj, out);
}

// round 7
// speedup vs baseline: 3.2735x; 1.3220x over previous
#include <cuda_runtime.h>
#include <cstdint>

#define B_    15
#define NW_   64
#define NT    144
#define DIM   384
#define HEADS 12
#define HD    32
#define TOK   (B_ * NW_ * NT)     // 138240
#define QKVC  (3 * DIM)           // 1152
#define WH    (NW_ * HEADS)       // 768
#define NTSQ  (NT * NT)           // 20736

// ---- device scratch ----
__device__ float g_x[(size_t)TOK * DIM];          // tf32-rounded x
__device__ float g_q[(size_t)B_ * NW_ * HEADS * NT * HD];   // rounded, scaled
__device__ float g_k[(size_t)B_ * NW_ * HEADS * NT * HD];   // rounded
__device__ float g_vT[(size_t)B_ * NW_ * HEADS * HD * NT];  // rounded, [bwh][d][n]
__device__ float g_ao[(size_t)TOK * DIM];         // rounded attention output
__device__ float g_wT_qkv[(size_t)QKVC * DIM];    // [n][k], rounded
__device__ float g_wT_proj[(size_t)DIM * DIM];    // [n][k], rounded
__device__ float g_bias[(size_t)WH * NTSQ];       // [w*H+h][i*144+j]

// ---------------------------------------------------------------------------
__device__ __forceinline__ uint32_t smem_u32(const void* p) {
    uint32_t a;
    asm("{ .reg .u64 t; cvta.to.shared.u64 t, %1; cvt.u32.u64 %0, t; }"
        : "=r"(a) : "l"(p));
    return a;
}
__device__ __forceinline__ float to_tf32(float x) {
    float r;
    asm("cvt.rna.tf32.f32 %0, %1;" : "=f"(r) : "f"(x));
    return r;
}
__device__ __forceinline__ void cpa16(uint32_t dst, const void* src) {
    asm volatile("cp.async.ca.shared.global [%0], [%1], 16;"
                 :: "r"(dst), "l"(src) : "memory");
}
#define CP_COMMIT() asm volatile("cp.async.commit_group;" ::: "memory")
#define CP_WAIT(n)  asm volatile("cp.async.wait_group %0;" :: "n"(n) : "memory")

__device__ __forceinline__ void ldsm4(uint32_t* r, uint32_t addr) {
    asm volatile("ldmatrix.sync.aligned.m8n8.x4.shared.b16 {%0,%1,%2,%3}, [%4];"
                 : "=r"(r[0]), "=r"(r[1]), "=r"(r[2]), "=r"(r[3]) : "r"(addr));
}
__device__ __forceinline__ void mma_tf32(float* c, const uint32_t* a,
                                         uint32_t b0, uint32_t b1) {
    asm volatile(
        "mma.sync.aligned.m16n8k8.row.col.f32.tf32.tf32.f32 "
        "{%0,%1,%2,%3}, {%4,%5,%6,%7}, {%8,%9}, {%0,%1,%2,%3};"
        : "+f"(c[0]), "+f"(c[1]), "+f"(c[2]), "+f"(c[3])
        : "r"(a[0]), "r"(a[1]), "r"(a[2]), "r"(a[3]), "r"(b0), "r"(b1));
}

// ---------------------------------------------------------------------------
__global__ void prep_x_kernel(const float* __restrict__ x) {
    size_t i = (size_t)blockIdx.x * 256 + threadIdx.x;
    float4 v = ((const float4*)x)[i];
    v.x = to_tf32(v.x); v.y = to_tf32(v.y);
    v.z = to_tf32(v.z); v.w = to_tf32(v.w);
    ((float4*)g_x)[i] = v;
}

__global__ void prep_w_kernel(const float* __restrict__ wq,
                              const float* __restrict__ wp) {
    int i = blockIdx.x * blockDim.x + threadIdx.x;
    if (i < QKVC * DIM) {
        int n = i / DIM, k = i % DIM;
        g_wT_qkv[i] = to_tf32(wq[(size_t)k * QKVC + n]);
    } else {
        int j = i - QKVC * DIM;
        if (j < DIM * DIM) {
            int n = j / DIM, k = j % DIM;
            g_wT_proj[j] = to_tf32(wp[(size_t)k * DIM + n]);
        }
    }
}

// g_bias[wh][ij] = bias_table[pi[ij]*768 + wh] via smem transpose.
__global__ void prep_bias_kernel(const float* __restrict__ bt,
                                 const int* __restrict__ pi) {
    __shared__ float t[32][33];
    const int tx = threadIdx.x, ty = threadIdx.y;
    const int ij = blockIdx.x * 32 + ty;
    const int wh = blockIdx.y * 32 + tx;
    t[ty][tx] = __ldg(&bt[(size_t)__ldg(&pi[ij]) * WH + wh]);
    __syncthreads();
    const int wh_o = blockIdx.y * 32 + ty;
    const int ij_o = blockIdx.x * 32 + tx;
    g_bias[(size_t)wh_o * NTSQ + ij_o] = t[tx][ty];
}

// ---------------------------------------------------------------------------
// tf32 mma.sync GEMM, 4-stage cp.async pipeline. 128x128 tile, BK=16, 8 warps.
// Dyn smem: A stages [0,40960) B stages [40960,81920), stage stride 10240 B.
// MODE 0: A=g_x, B=g_wT_qkv -> q/k rounded(+scale), V rounded+transposed.
// MODE 1: A=g_ao, B=g_wT_proj -> out (+bias).
// ---------------------------------------------------------------------------
#define BPITCH 20
template <int NTOT, int MODE>
__global__ __launch_bounds__(256, 2) void gemm_mma_kernel(
    const float* __restrict__ bias, float* __restrict__ out)
{
    extern __shared__ float gsm[];
    const uint32_t base = smem_u32(gsm);

    const int tid = threadIdx.x;
    const int wid = tid >> 5;
    const int lane = tid & 31;
    const int warp_m = wid >> 1;
    const int warp_n = wid & 1;
    const int bn = blockIdx.x * 128;
    const int bm = blockIdx.y * 128;

    // device-side symbol selection (host cannot pass __device__ symbols!)
    const float* Ap = (MODE == 0) ? g_x : g_ao;
    const float* Bt = (MODE == 0) ? g_wT_qkv : g_wT_proj;

    const int r0 = tid >> 2;             // 0..63
    const int c40 = (tid & 3) << 2;      // 0,4,8,12

    float acc[2][8][4];
#pragma unroll
    for (int mt = 0; mt < 2; mt++)
#pragma unroll
        for (int nt = 0; nt < 8; nt++)
#pragma unroll
            for (int i = 0; i < 4; i++) acc[mt][nt][i] = 0.f;

    const int rowA_off = (warp_m * 32 + (lane & 15)) * BPITCH + (lane >> 4) * 4;
    const int rowB_off = (warp_n * 64 + (lane & 15)) * BPITCH + (lane >> 4) * 4;

    auto issue = [&](int s) {
        const int p = s & 3;
        const int k0 = s * 16;
        const uint32_t a_dst = base + (uint32_t)(p * 10240 + (r0 * BPITCH + c40) * 4);
        cpa16(a_dst, Ap + (size_t)(bm + r0) * DIM + k0 + c40);
        cpa16(a_dst + 64 * BPITCH * 4, Ap + (size_t)(bm + r0 + 64) * DIM + k0 + c40);
        const uint32_t b_dst = a_dst + 40960u;
        cpa16(b_dst, Bt + (size_t)(bn + r0) * DIM + k0 + c40);
        cpa16(b_dst + 64 * BPITCH * 4, Bt + (size_t)(bn + r0 + 64) * DIM + k0 + c40);
    };

    const int NSTAGE = DIM / 16;   // 24
#pragma unroll
    for (int s = 0; s < 3; s++) { issue(s); CP_COMMIT(); }

    for (int s = 0; s < NSTAGE; s++) {
        CP_WAIT(2);
        __syncthreads();
        if (s < NSTAGE - 3) issue(s + 3);
        CP_COMMIT();

        const int p = s & 3;
        const uint32_t sA = base + p * 10240;
        const uint32_t sB = base + 40960 + p * 10240;
#pragma unroll
        for (int kk = 0; kk < 2; kk++) {
            uint32_t ua[2][4], ub[4][4];
#pragma unroll
            for (int mt = 0; mt < 2; mt++)
                ldsm4(ua[mt], sA + (rowA_off + mt * 16 * BPITCH + kk * 8) * 4);
#pragma unroll
            for (int g = 0; g < 4; g++)
                ldsm4(ub[g], sB + (rowB_off + g * 16 * BPITCH + kk * 8) * 4);
#pragma unroll
            for (int mt = 0; mt < 2; mt++)
#pragma unroll
                for (int nt = 0; nt < 8; nt++)
                    mma_tf32(acc[mt][nt], ua[mt], ub[nt >> 1][nt & 1],
                             ub[nt >> 1][(nt & 1) + 2]);
        }
    }

    // ---------------- epilogue ----------------
    const int colb = warp_n * 64 + 2 * (lane & 3);
    if (MODE == 0) {
        const int which = bn / DIM;
        const float sc = (which == 0) ? 0.17677669529663687f : 1.0f;
        const int rembase = (bn - which * DIM) + colb;
#pragma unroll
        for (int nt = 0; nt < 8; nt++) {
            const int rem = rembase + nt * 8;
            const int hh = rem >> 5, dd = rem & 31;
            const float b0 = __ldg(&bias[which * DIM + rem]);
            const float b1 = __ldg(&bias[which * DIM + rem + 1]);
#pragma unroll
            for (int mt = 0; mt < 2; mt++) {
#pragma unroll
                for (int rr = 0; rr < 2; rr++) {
                    const int m = bm + warp_m * 32 + mt * 16 + (lane >> 2) + rr * 8;
                    const int bw = m / NT, n = m - (m / NT) * NT;
                    const float v0 = to_tf32((acc[mt][nt][rr * 2 + 0] + b0) * sc);
                    const float v1 = to_tf32((acc[mt][nt][rr * 2 + 1] + b1) * sc);
                    if (which < 2) {
                        float* dst = (which == 0) ? g_q : g_k;
                        float2 v; v.x = v0; v.y = v1;
                        *(float2*)&dst[((size_t)(bw * HEADS + hh) * NT + n) * HD + dd] = v;
                    } else {
                        float* dv = &g_vT[((size_t)(bw * HEADS + hh) * HD + dd) * NT + n];
                        dv[0] = v0;
                        dv[NT] = v1;
                    }
                }
            }
        }
    } else {
#pragma unroll
        for (int nt = 0; nt < 8; nt++) {
            const int col = bn + colb + nt * 8;
            const float b0 = __ldg(&bias[col]);
            const float b1 = __ldg(&bias[col + 1]);
#pragma unroll
            for (int mt = 0; mt < 2; mt++) {
#pragma unroll
                for (int rr = 0; rr < 2; rr++) {
                    const int m = bm + warp_m * 32 + mt * 16 + (lane >> 2) + rr * 8;
                    float2 v;
                    v.x = acc[mt][nt][rr * 2 + 0] + b0;
                    v.y = acc[mt][nt][rr * 2 + 1] + b1;
                    *(float2*)&out[(size_t)m * DIM + col] = v;
                }
            }
        }
    }
}

// ---------------------------------------------------------------------------
// Tensor-core attention, fully cp.async staged.
// Block = (b,w,h), 288 threads. Q/K/Vt + bias tile all cp.async'd; bias lands
// in the P buffer and is consumed/overwritten in place by the softmax epilogue.
// ---------------------------------------------------------------------------
#define QK_PITCH 36
#define P_PITCH  148
#define SM_Q  0
#define SM_K  (NT * QK_PITCH)                 // 5184
#define SM_VT (SM_K + NT * QK_PITCH)          // 10368
#define SM_P  (SM_VT + HD * P_PITCH)          // 15104
#define SM_TOT_F (SM_P + NT * P_PITCH)        // 36416 floats = 145664 B

__global__ __launch_bounds__(288, 1) void attn_mma_kernel(
    const float* __restrict__ mask)
{
    extern __shared__ float sm[];
    float* Ps = sm + SM_P;

    const int bx = blockIdx.x;
    const int h = bx % HEADS;
    const int w = (bx / HEADS) % NW_;
    const int b = bx / WH;
    const int bw = b * NW_ + w;
    const size_t head_base = (size_t)(bw * HEADS + h) * NT * HD;

    const int tid = threadIdx.x;
    const int wid = tid >> 5;
    const int lane = tid & 31;

    const uint32_t sQ = smem_u32(sm);
    const uint32_t sK = sQ + SM_K * 4;
    const uint32_t sV = sQ + SM_VT * 4;
    const uint32_t sP = sQ + SM_P * 4;

    // ---- group 0: Q, K, Vt ----
#pragma unroll
    for (int it = 0; it < 4; it++) {
        const int i = tid + it * 288;
        const int r = i >> 3, c4 = (i & 7) << 2;               // Q/K: 144x32
        cpa16(sQ + (uint32_t)(r * QK_PITCH + c4) * 4, g_q + head_base + (size_t)r * HD + c4);
        cpa16(sK + (uint32_t)(r * QK_PITCH + c4) * 4, g_k + head_base + (size_t)r * HD + c4);
        const int d = i / 36, c = (i % 36) << 2;               // Vt: 32x144
        cpa16(sV + (uint32_t)(d * P_PITCH + c) * 4, g_vT + head_base + (size_t)d * NT + c);
    }
    CP_COMMIT();

    // ---- group 1: bias tile into Ps ----
    const float* bp = g_bias + (size_t)(w * HEADS + h) * NTSQ;
#pragma unroll
    for (int it = 0; it < 18; it++) {
        const int i = tid + it * 288;
        const int r = i / 36, c = (i % 36) << 2;
        cpa16(sP + (uint32_t)(r * P_PITCH + c) * 4, bp + (size_t)r * NT + c);
    }
    CP_COMMIT();

    CP_WAIT(1);              // Q/K/Vt ready; bias may still be in flight
    __syncthreads();

    const int i0 = wid * 16;
    const int lrow = lane >> 2;
    const int lcol = (lane & 3) * 2;

    // ---- Phase 1: S = Q @ K^T ----
    float acc[18][4];
#pragma unroll
    for (int nt = 0; nt < 18; nt++)
#pragma unroll
        for (int e = 0; e < 4; e++) acc[nt][e] = 0.f;

#pragma unroll
    for (int ks = 0; ks < 4; ks++) {
        uint32_t ua[4];
        ldsm4(ua, sQ + (uint32_t)((i0 + (lane & 15)) * QK_PITCH + (lane >> 4) * 4 + ks * 8) * 4);
#pragma unroll
        for (int g = 0; g < 9; g++) {
            uint32_t ub[4];
            ldsm4(ub, sK + (uint32_t)((g * 16 + (lane & 15)) * QK_PITCH + (lane >> 4) * 4 + ks * 8) * 4);
            mma_tf32(acc[2 * g + 0], ua, ub[0], ub[2]);
            mma_tf32(acc[2 * g + 1], ua, ub[1], ub[3]);
        }
    }

    CP_WAIT(0);              // bias tile landed
    __syncthreads();

    // ---- softmax epilogue: bias (smem, in place) + mask, exp, row sums ----
    const float* mp = mask + (size_t)b * NTSQ;
    const int r0 = i0 + lrow;
    const int r1 = r0 + 8;
    float s0 = 0.f, s1 = 0.f;
#pragma unroll
    for (int nt = 0; nt < 18; nt++) {
        const int j = nt * 8 + lcol;
        const float2 bb0 = *(const float2*)&Ps[r0 * P_PITCH + j];
        const float2 bb1 = *(const float2*)&Ps[r1 * P_PITCH + j];
        const float2 mm0 = *(const float2*)&mp[(size_t)r0 * NT + j];
        const float2 mm1 = *(const float2*)&mp[(size_t)r1 * NT + j];
        float p00 = __expf(acc[nt][0] + bb0.x + mm0.x);
        float p01 = __expf(acc[nt][1] + bb0.y + mm0.y);
        float p10 = __expf(acc[nt][2] + bb1.x + mm1.x);
        float p11 = __expf(acc[nt][3] + bb1.y + mm1.y);
        s0 += p00 + p01;
        s1 += p10 + p11;
        float2 w0; w0.x = to_tf32(p00); w0.y = to_tf32(p01);
        float2 w1; w1.x = to_tf32(p10); w1.y = to_tf32(p11);
        *(float2*)&Ps[r0 * P_PITCH + j] = w0;
        *(float2*)&Ps[r1 * P_PITCH + j] = w1;
    }
    s0 += __shfl_xor_sync(0xffffffffu, s0, 1);
    s0 += __shfl_xor_sync(0xffffffffu, s0, 2);
    s1 += __shfl_xor_sync(0xffffffffu, s1, 1);
    s1 += __shfl_xor_sync(0xffffffffu, s1, 2);
    const float inv0 = 1.f / s0;
    const float inv1 = 1.f / s1;

    __syncthreads();

    // ---- Phase 2: O = P @ V ----
    float oc[4][4];
#pragma unroll
    for (int nt = 0; nt < 4; nt++)
#pragma unroll
        for (int e = 0; e < 4; e++) oc[nt][e] = 0.f;

#pragma unroll
    for (int ks = 0; ks < 18; ks++) {
        uint32_t ua[4], ub0[4], ub1[4];
        ldsm4(ua, sP + (uint32_t)((i0 + (lane & 15)) * P_PITCH + (lane >> 4) * 4 + ks * 8) * 4);
        ldsm4(ub0, sV + (uint32_t)(((lane & 15)) * P_PITCH + (lane >> 4) * 4 + ks * 8) * 4);
        ldsm4(ub1, sV + (uint32_t)((16 + (lane & 15)) * P_PITCH + (lane >> 4) * 4 + ks * 8) * 4);
        mma_tf32(oc[0], ua, ub0[0], ub0[2]);
        mma_tf32(oc[1], ua, ub0[1], ub0[3]);
        mma_tf32(oc[2], ua, ub1[0], ub1[2]);
        mma_tf32(oc[3], ua, ub1[1], ub1[3]);
    }

    // ---- write O (normalized, tf32-rounded for proj GEMM) ----
#pragma unroll
    for (int nt = 0; nt < 4; nt++) {
        const int d = nt * 8 + lcol;
        float2 v0; v0.x = to_tf32(oc[nt][0] * inv0); v0.y = to_tf32(oc[nt][1] * inv0);
        float2 v1; v1.x = to_tf32(oc[nt][2] * inv1); v1.y = to_tf32(oc[nt][3] * inv1);
        *(float2*)&g_ao[((size_t)(bw * NT) + r0) * DIM + h * HD + d] = v0;
        *(float2*)&g_ao[((size_t)(bw * NT) + r1) * DIM + h * HD + d] = v1;
    }
}

// ---------------------------------------------------------------------------
extern "C" void kernel_launch(void* const* d_in, const int* in_sizes, int n_in,
                              void* d_out, int out_size)
{
    const float* x          = (const float*)d_in[0];
    const float* mask       = (const float*)d_in[1];
    const float* w_qkv      = (const float*)d_in[2];
    const float* b_qkv      = (const float*)d_in[3];
    const float* w_proj     = (const float*)d_in[4];
    const float* b_proj     = (const float*)d_in[5];
    const float* bias_table = (const float*)d_in[6];
    const int*   pi         = (const int*)d_in[7];
    float* out = (float*)d_out;

    const int GEMM_SMEM = 81920;
    const int ATTN_SMEM = SM_TOT_F * 4;   // 145664
    cudaFuncSetAttribute(gemm_mma_kernel<QKVC, 0>,
                         cudaFuncAttributeMaxDynamicSharedMemorySize, GEMM_SMEM);
    cudaFuncSetAttribute(gemm_mma_kernel<DIM, 1>,
                         cudaFuncAttributeMaxDynamicSharedMemorySize, GEMM_SMEM);
    cudaFuncSetAttribute(attn_mma_kernel,
                         cudaFuncAttributeMaxDynamicSharedMemorySize, ATTN_SMEM);

    prep_x_kernel<<<(TOK * DIM / 4) / 256, 256>>>(x);
    prep_w_kernel<<<(QKVC * DIM + DIM * DIM + 255) / 256, 256>>>(w_qkv, w_proj);

    dim3 bt(32, 32);
    dim3 bg(NTSQ / 32, WH / 32);
    prep_bias_kernel<<<bg, bt>>>(bias_table, pi);

    dim3 g1(QKVC / 128, TOK / 128);
    gemm_mma_kernel<QKVC, 0><<<g1, 256, GEMM_SMEM>>>(b_qkv, out);

    attn_mma_kernel<<<B_ * WH, 288, ATTN_SMEM>>>(mask);

    dim3 g2(DIM / 128, TOK / 128);
    gemm_mma_kernel<DIM, 1><<<g2, 256, GEMM_SMEM>>>(b_proj, out);
}